// round 6
// baseline (speedup 1.0000x reference)
#include <cuda_runtime.h>
#include <cuda_bf16.h>
#include <math.h>

#define HIDDEN 128
#define MAX_ING 20000
#define MAX_CMP 10000
#define NBLOCKS 592   // 4 blocks/SM x 148 SMs; guaranteed co-resident via launch_bounds

// Precomputed per-node projections in bf16 (L2-resident: 5MB + 2.5MB)
__device__ __nv_bfloat16 g_P_ing[MAX_ING * HIDDEN];
__device__ __nv_bfloat16 g_P_cmp[MAX_CMP * HIDDEN];

// Monotonic epoch barrier counter (zero-init at module load; replay-safe).
__device__ unsigned int g_bar;

__device__ __forceinline__ void fma4(float4& a, float xs, const float4 w) {
    a.x = fmaf(xs, w.x, a.x);
    a.y = fmaf(xs, w.y, a.y);
    a.z = fmaf(xs, w.z, a.z);
    a.w = fmaf(xs, w.w, a.w);
}

// fp32 projection of one 64-row tile (8 rows per warp register blocking).
__device__ __forceinline__ void proj_tile(
    const float* __restrict__ X, const float* __restrict__ W,
    const float* __restrict__ b1, __nv_bfloat16* __restrict__ P,
    int nrows, int bid, bool add_bias)
{
    const int warp = threadIdx.x >> 5;
    const int lane = threadIdx.x & 31;
    const int row0 = bid * 64 + warp * 8;
    if (row0 >= nrows) return;

    int r[8];
    #pragma unroll
    for (int i = 0; i < 8; i++) r[i] = min(row0 + i, nrows - 1);

    const float4* __restrict__ W4 = reinterpret_cast<const float4*>(W);  // [128][32]
    const float4* __restrict__ X4 = reinterpret_cast<const float4*>(X);  // [nrows][32]

    float4 acc[8];
    #pragma unroll
    for (int i = 0; i < 8; i++) acc[i] = make_float4(0.f, 0.f, 0.f, 0.f);

    #pragma unroll 2
    for (int k4 = 0; k4 < 32; k4++) {
        const float4 w0 = W4[(k4 * 4 + 0) * 32 + lane];
        const float4 w1 = W4[(k4 * 4 + 1) * 32 + lane];
        const float4 w2 = W4[(k4 * 4 + 2) * 32 + lane];
        const float4 w3 = W4[(k4 * 4 + 3) * 32 + lane];
        #pragma unroll
        for (int i = 0; i < 8; i++) {
            const float4 x = X4[(size_t)r[i] * 32 + k4];
            fma4(acc[i], x.x, w0);
            fma4(acc[i], x.y, w1);
            fma4(acc[i], x.z, w2);
            fma4(acc[i], x.w, w3);
        }
    }

    if (add_bias) {
        const float4 bv = reinterpret_cast<const float4*>(b1)[lane];
        #pragma unroll
        for (int i = 0; i < 8; i++) {
            acc[i].x += bv.x; acc[i].y += bv.y;
            acc[i].z += bv.z; acc[i].w += bv.w;
        }
    }

    uint2* P2 = reinterpret_cast<uint2*>(P);
    #pragma unroll
    for (int i = 0; i < 8; i++) {
        if (row0 + i < nrows) {
            __nv_bfloat162 lo = __float22bfloat162_rn(make_float2(acc[i].x, acc[i].y));
            __nv_bfloat162 hi = __float22bfloat162_rn(make_float2(acc[i].z, acc[i].w));
            uint2 v;
            v.x = *reinterpret_cast<unsigned int*>(&lo);
            v.y = *reinterpret_cast<unsigned int*>(&hi);
            P2[(size_t)r[i] * 32 + lane] = v;
        }
    }
}

// dot of lane's 16 columns for one edge; packed f32x2 FFMA (sm_103a FFMA2).
__device__ __forceinline__ float edge_slice_dot(
    int s, int d, int t, const unsigned long long* __restrict__ wp)
{
    const char* pa = (const char*)g_P_ing + (size_t)s * 256 + t * 16;
    const char* pb = (const char*)g_P_cmp + (size_t)d * 256 + t * 16;
    const uint4 al = *reinterpret_cast<const uint4*>(pa);         // line 0
    const uint4 ah = *reinterpret_cast<const uint4*>(pa + 128);   // line 1
    const uint4 bl = *reinterpret_cast<const uint4*>(pb);
    const uint4 bh = *reinterpret_cast<const uint4*>(pb + 128);

    const __nv_bfloat162 z2 = __float2bfloat162_rn(0.f);
    const unsigned av[8] = {al.x, al.y, al.z, al.w, ah.x, ah.y, ah.z, ah.w};
    const unsigned bv[8] = {bl.x, bl.y, bl.z, bl.w, bh.x, bh.y, bh.z, bh.w};

    unsigned long long acc2 = 0ull;  // packed {0.f, 0.f}
    #pragma unroll
    for (int j = 0; j < 8; j++) {
        __nv_bfloat162 ha = *reinterpret_cast<const __nv_bfloat162*>(&av[j]);
        __nv_bfloat162 hb = *reinterpret_cast<const __nv_bfloat162*>(&bv[j]);
        __nv_bfloat162 h2 = __hmax2(__hadd2(ha, hb), z2);   // add + relu in bf16
        const unsigned hv = *reinterpret_cast<const unsigned*>(&h2);
        const unsigned flo = hv << 16;            // low bf16 -> fp32 bits
        const unsigned fhi = hv & 0xFFFF0000u;    // high bf16 -> fp32 bits
        unsigned long long hp;
        asm("mov.b64 %0, {%1, %2};" : "=l"(hp) : "r"(flo), "r"(fhi));
        asm("fma.rn.f32x2 %0, %1, %2, %0;" : "+l"(acc2) : "l"(hp), "l"(wp[j]));
    }
    unsigned lo32, hi32;
    asm("mov.b64 {%0, %1}, %2;" : "=r"(lo32), "=r"(hi32) : "l"(acc2));
    return __uint_as_float(lo32) + __uint_as_float(hi32);
}

__global__ void __launch_bounds__(256, 4) fused_kernel(
    const float* __restrict__ x_ing,
    const float* __restrict__ x_cmp,
    const int* __restrict__ ei,
    const float* __restrict__ W1,
    const float* __restrict__ b1,
    const float* __restrict__ W2,
    const float* __restrict__ b2,
    float* __restrict__ out,
    int n_ing, int n_cmp, int E,
    int blocks_ing, int blocks_total)
{
    // ---------------- Phase A: projections (grid-stride over tiles) --------
    for (int tile = blockIdx.x; tile < blocks_total; tile += gridDim.x) {
        if (tile < blocks_ing)
            proj_tile(x_ing, W1, b1, g_P_ing, n_ing, tile, false);
        else
            proj_tile(x_cmp, W1 + HIDDEN * HIDDEN, b1, g_P_cmp, n_cmp,
                      tile - blocks_ing, true);
    }

    // ---------------- device-wide epoch barrier ----------------------------
    __threadfence();          // release P writes to L2
    __syncthreads();
    if (threadIdx.x == 0) {
        const unsigned int G = gridDim.x;
        const unsigned int ticket = atomicAdd(&g_bar, 1u);
        const unsigned int target = (ticket / G + 1u) * G;
        volatile unsigned int* p = &g_bar;
        while (*p < target) __nanosleep(64);
    }
    __syncthreads();

    // ---------------- Phase B: edges (grid-stride, 8 lanes/edge, 4 edges/grp)
    const int t = threadIdx.x & 7;

    // lane's W2 coefficients packed as f32x2 pairs:
    // cols [8t, 8t+8) (low half) and [64+8t, 64+8t+8) (high half)
    const float4* W24 = reinterpret_cast<const float4*>(W2);
    const float4 wl0 = __ldg(W24 + 2 * t + 0);
    const float4 wl1 = __ldg(W24 + 2 * t + 1);
    const float4 wh0 = __ldg(W24 + 16 + 2 * t + 0);
    const float4 wh1 = __ldg(W24 + 16 + 2 * t + 1);
    const float wv[16] = {wl0.x, wl0.y, wl0.z, wl0.w,
                          wl1.x, wl1.y, wl1.z, wl1.w,
                          wh0.x, wh0.y, wh0.z, wh0.w,
                          wh1.x, wh1.y, wh1.z, wh1.w};
    unsigned long long wp[8];
    #pragma unroll
    for (int j = 0; j < 8; j++) {
        asm("mov.b64 %0, {%1, %2};" : "=l"(wp[j])
            : "r"(__float_as_uint(wv[2 * j])), "r"(__float_as_uint(wv[2 * j + 1])));
    }
    const float b2v = __ldg(b2);

    const int ngroups = (E + 3) >> 2;
    const int gstride = (gridDim.x * blockDim.x) >> 3;
    for (int gid = (blockIdx.x * blockDim.x + threadIdx.x) >> 3;
         gid < ngroups; gid += gstride) {
        const int e0 = gid * 4;

        int sv[4], dv[4];
        int ne;
        if (e0 + 4 <= E) {
            ne = 4;
            const int4 s4 = __ldg(reinterpret_cast<const int4*>(ei + e0));
            const int4 d4 = __ldg(reinterpret_cast<const int4*>(ei + E + e0));
            sv[0] = s4.x; sv[1] = s4.y; sv[2] = s4.z; sv[3] = s4.w;
            dv[0] = d4.x; dv[1] = d4.y; dv[2] = d4.z; dv[3] = d4.w;
        } else {
            ne = E - e0;
            for (int i = 0; i < ne; i++) {
                sv[i] = __ldg(ei + e0 + i);
                dv[i] = __ldg(ei + E + e0 + i);
            }
            for (int i = ne; i < 4; i++) { sv[i] = 0; dv[i] = 0; }
        }

        float acc[4];
        #pragma unroll
        for (int i = 0; i < 4; i++)
            acc[i] = edge_slice_dot(sv[i], dv[i], t, wp);

        #pragma unroll
        for (int i = 0; i < 4; i++) {
            acc[i] += __shfl_xor_sync(0xFFFFFFFFu, acc[i], 1);
            acc[i] += __shfl_xor_sync(0xFFFFFFFFu, acc[i], 2);
            acc[i] += __shfl_xor_sync(0xFFFFFFFFu, acc[i], 4);
        }

        if (t == 0) {
            #pragma unroll
            for (int i = 0; i < 4; i++) {
                if (i < ne) {
                    const float z = acc[i] + b2v;
                    out[e0 + i] = 1.f / (1.f + __expf(-z));
                }
            }
        }
    }
}

extern "C" void kernel_launch(void* const* d_in, const int* in_sizes, int n_in,
                              void* d_out, int out_size)
{
    const float* x_ing = (const float*)d_in[0];
    const float* x_cmp = (const float*)d_in[1];
    const int*   ei    = (const int*)d_in[2];
    const float* W1    = (const float*)d_in[3];
    const float* b1    = (const float*)d_in[4];
    const float* W2    = (const float*)d_in[5];
    const float* b2    = (const float*)d_in[6];
    float* out = (float*)d_out;

    const int n_ing = in_sizes[0] / HIDDEN;
    const int n_cmp = in_sizes[1] / HIDDEN;
    const int E     = in_sizes[2] / 2;

    const int blocks_ing = (n_ing + 63) / 64;
    const int blocks_cmp = (n_cmp + 63) / 64;

    fused_kernel<<<NBLOCKS, 256>>>(x_ing, x_cmp, ei, W1, b1, W2, b2, out,
                                   n_ing, n_cmp, E,
                                   blocks_ing, blocks_ing + blocks_cmp);
}

// round 7
// speedup vs baseline: 1.6893x; 1.6893x over previous
#include <cuda_runtime.h>
#include <cuda_bf16.h>
#include <math.h>

#define HIDDEN 128
#define MAX_ING 20000
#define MAX_CMP 10000

// Precomputed per-node projections in bf16 (L2-resident: 5MB + 2.5MB)
__device__ __nv_bfloat16 g_P_ing[MAX_ING * HIDDEN];
__device__ __nv_bfloat16 g_P_cmp[MAX_CMP * HIDDEN];

__device__ __forceinline__ void fma4(float4& a, float xs, const float4 w) {
    a.x = fmaf(xs, w.x, a.x);
    a.y = fmaf(xs, w.y, a.y);
    a.z = fmaf(xs, w.z, a.z);
    a.w = fmaf(xs, w.w, a.w);
}

// Fused projection of both node tables (R4-proven version, unchanged).
__global__ void __launch_bounds__(256) proj_kernel(
    const float* __restrict__ x_ing,
    const float* __restrict__ x_cmp,
    const float* __restrict__ W1,
    const float* __restrict__ b1,
    int n_ing, int n_cmp, int blocks_ing)
{
    const bool is_cmp = (blockIdx.x >= blocks_ing);
    const float* __restrict__ X = is_cmp ? x_cmp : x_ing;
    const float* __restrict__ W = is_cmp ? (W1 + HIDDEN * HIDDEN) : W1;
    __nv_bfloat16* __restrict__ P = is_cmp ? g_P_cmp : g_P_ing;
    const int nrows = is_cmp ? n_cmp : n_ing;
    const int bid = is_cmp ? (blockIdx.x - blocks_ing) : blockIdx.x;

    const int warp = threadIdx.x >> 5;
    const int lane = threadIdx.x & 31;
    const int row0 = bid * 64 + warp * 8;
    if (row0 >= nrows) return;

    int r[8];
    #pragma unroll
    for (int i = 0; i < 8; i++) r[i] = min(row0 + i, nrows - 1);

    const float4* __restrict__ W4 = reinterpret_cast<const float4*>(W);  // [128][32]
    const float4* __restrict__ X4 = reinterpret_cast<const float4*>(X);  // [nrows][32]

    float4 acc[8];
    #pragma unroll
    for (int i = 0; i < 8; i++) acc[i] = make_float4(0.f, 0.f, 0.f, 0.f);

    #pragma unroll 2
    for (int k4 = 0; k4 < 32; k4++) {
        const float4 w0 = W4[(k4 * 4 + 0) * 32 + lane];
        const float4 w1 = W4[(k4 * 4 + 1) * 32 + lane];
        const float4 w2 = W4[(k4 * 4 + 2) * 32 + lane];
        const float4 w3 = W4[(k4 * 4 + 3) * 32 + lane];
        #pragma unroll
        for (int i = 0; i < 8; i++) {
            const float4 x = X4[(size_t)r[i] * 32 + k4];
            fma4(acc[i], x.x, w0);
            fma4(acc[i], x.y, w1);
            fma4(acc[i], x.z, w2);
            fma4(acc[i], x.w, w3);
        }
    }

    if (is_cmp) {
        const float4 bv = reinterpret_cast<const float4*>(b1)[lane];
        #pragma unroll
        for (int i = 0; i < 8; i++) {
            acc[i].x += bv.x; acc[i].y += bv.y;
            acc[i].z += bv.z; acc[i].w += bv.w;
        }
    }

    uint2* P2 = reinterpret_cast<uint2*>(P);
    #pragma unroll
    for (int i = 0; i < 8; i++) {
        if (row0 + i < nrows) {
            __nv_bfloat162 lo = __float22bfloat162_rn(make_float2(acc[i].x, acc[i].y));
            __nv_bfloat162 hi = __float22bfloat162_rn(make_float2(acc[i].z, acc[i].w));
            uint2 v;
            v.x = *reinterpret_cast<unsigned int*>(&lo);
            v.y = *reinterpret_cast<unsigned int*>(&hi);
            P2[(size_t)r[i] * 32 + lane] = v;
        }
    }
}

// ---------------------------------------------------------------------------
// Edge kernel v5: 8 lanes/edge, 4 edges/group, contiguous 128B-line loads
// (R4 layout), bit-shift bf16->fp32 unpack (ALU, no CVT), fp32 FFMA dot,
// 3-shuffle reduce. minblocks=6 to force <=42 regs -> higher occupancy.
// ---------------------------------------------------------------------------
__device__ __forceinline__ float edge_slice_dot(
    int s, int d, int t, const float* __restrict__ wv)
{
    const char* pa = (const char*)g_P_ing + (size_t)s * 256 + t * 16;
    const char* pb = (const char*)g_P_cmp + (size_t)d * 256 + t * 16;
    const uint4 al = *reinterpret_cast<const uint4*>(pa);         // line 0
    const uint4 ah = *reinterpret_cast<const uint4*>(pa + 128);   // line 1
    const uint4 bl = *reinterpret_cast<const uint4*>(pb);
    const uint4 bh = *reinterpret_cast<const uint4*>(pb + 128);

    const __nv_bfloat162 z2 = __float2bfloat162_rn(0.f);
    const unsigned av[8] = {al.x, al.y, al.z, al.w, ah.x, ah.y, ah.z, ah.w};
    const unsigned bv[8] = {bl.x, bl.y, bl.z, bl.w, bh.x, bh.y, bh.z, bh.w};

    float acc = 0.f;
    #pragma unroll
    for (int j = 0; j < 8; j++) {
        __nv_bfloat162 ha = *reinterpret_cast<const __nv_bfloat162*>(&av[j]);
        __nv_bfloat162 hb = *reinterpret_cast<const __nv_bfloat162*>(&bv[j]);
        __nv_bfloat162 h2 = __hmax2(__hadd2(ha, hb), z2);   // add + relu in bf16
        const unsigned hu = *reinterpret_cast<const unsigned*>(&h2);
        const float flo = __uint_as_float(hu << 16);         // low bf16 -> fp32
        const float fhi = __uint_as_float(hu & 0xFFFF0000u); // high bf16 -> fp32
        acc = fmaf(flo, wv[2 * j], acc);
        acc = fmaf(fhi, wv[2 * j + 1], acc);
    }
    return acc;
}

__global__ void __launch_bounds__(256, 6) edge_kernel(
    const int* __restrict__ ei,
    const float* __restrict__ W2,
    const float* __restrict__ b2,
    float* __restrict__ out,
    int E)
{
    const int gid = (blockIdx.x * 256 + threadIdx.x) >> 3;  // global group id
    const int t = threadIdx.x & 7;                           // sublane in group
    const int e0 = gid * 4;
    if (e0 >= E) return;

    // lane's W2 coefficients: cols [8t,8t+8) and [64+8t,64+8t+8)
    const float4* W24 = reinterpret_cast<const float4*>(W2);
    const float4 wl0 = __ldg(W24 + 2 * t + 0);
    const float4 wl1 = __ldg(W24 + 2 * t + 1);
    const float4 wh0 = __ldg(W24 + 16 + 2 * t + 0);
    const float4 wh1 = __ldg(W24 + 16 + 2 * t + 1);
    const float wv[16] = {wl0.x, wl0.y, wl0.z, wl0.w,
                          wl1.x, wl1.y, wl1.z, wl1.w,
                          wh0.x, wh0.y, wh0.z, wh0.w,
                          wh1.x, wh1.y, wh1.z, wh1.w};
    const float b2v = __ldg(b2);

    int sv[4], dv[4];
    int ne;
    if (e0 + 4 <= E) {
        ne = 4;
        const int4 s4 = __ldg(reinterpret_cast<const int4*>(ei + e0));
        const int4 d4 = __ldg(reinterpret_cast<const int4*>(ei + E + e0));
        sv[0] = s4.x; sv[1] = s4.y; sv[2] = s4.z; sv[3] = s4.w;
        dv[0] = d4.x; dv[1] = d4.y; dv[2] = d4.z; dv[3] = d4.w;
    } else {
        ne = E - e0;
        for (int i = 0; i < ne; i++) {
            sv[i] = __ldg(ei + e0 + i);
            dv[i] = __ldg(ei + E + e0 + i);
        }
        for (int i = ne; i < 4; i++) { sv[i] = 0; dv[i] = 0; }
    }

    float acc[4];
    #pragma unroll
    for (int i = 0; i < 4; i++)
        acc[i] = edge_slice_dot(sv[i], dv[i], t, wv);

    #pragma unroll
    for (int i = 0; i < 4; i++) {
        acc[i] += __shfl_xor_sync(0xFFFFFFFFu, acc[i], 1);
        acc[i] += __shfl_xor_sync(0xFFFFFFFFu, acc[i], 2);
        acc[i] += __shfl_xor_sync(0xFFFFFFFFu, acc[i], 4);
    }

    if (t == 0) {
        #pragma unroll
        for (int i = 0; i < 4; i++) {
            if (i < ne) {
                const float z = acc[i] + b2v;
                out[e0 + i] = 1.f / (1.f + __expf(-z));
            }
        }
    }
}

extern "C" void kernel_launch(void* const* d_in, const int* in_sizes, int n_in,
                              void* d_out, int out_size)
{
    const float* x_ing = (const float*)d_in[0];
    const float* x_cmp = (const float*)d_in[1];
    const int*   ei    = (const int*)d_in[2];
    const float* W1    = (const float*)d_in[3];
    const float* b1    = (const float*)d_in[4];
    const float* W2    = (const float*)d_in[5];
    const float* b2    = (const float*)d_in[6];
    float* out = (float*)d_out;

    const int n_ing = in_sizes[0] / HIDDEN;
    const int n_cmp = in_sizes[1] / HIDDEN;
    const int E     = in_sizes[2] / 2;

    const int blocks_ing = (n_ing + 63) / 64;
    const int blocks_cmp = (n_cmp + 63) / 64;
    proj_kernel<<<blocks_ing + blocks_cmp, 256>>>(x_ing, x_cmp, W1, b1,
                                                  n_ing, n_cmp, blocks_ing);

    const int blocks = (E + 127) / 128;  // 128 edges per 256-thread block
    edge_kernel<<<blocks, 256>>>(ei, W2, b2, out, E);
}

// round 8
// speedup vs baseline: 2.0773x; 1.2296x over previous
#include <cuda_runtime.h>
#include <cuda_bf16.h>
#include <mma.h>
#include <math.h>

using namespace nvcuda;

#define HIDDEN 128
#define MAX_ING 20000
#define MAX_CMP 10000

// Precomputed per-node projections in bf16 (L2-resident: 5MB + 2.5MB)
__device__ __nv_bfloat16 g_P_ing[MAX_ING * HIDDEN];
__device__ __nv_bfloat16 g_P_cmp[MAX_CMP * HIDDEN];

// ---------------------------------------------------------------------------
// proj v3: tensor-core projection with fully SMEM-staged operands.
// P = X @ W (+bias for cmp), split-bf16: xh*Wh + xh*Wl + xl*Wh (exact to ~2e-5).
// Block: 256 threads, 64 rows x 128 cols. W half (128x128) split hi/lo inline.
// Dynamic smem: A_hi/A_lo (64x136 bf16) + W_hi/W_lo (128x136 bf16) = 104448B.
// ---------------------------------------------------------------------------
#define A_LD 136
#define W_LD 136
#define SM_A_ELEMS (64 * A_LD)
#define SM_W_ELEMS (128 * W_LD)
#define PROJ_SMEM_BYTES ((2 * SM_A_ELEMS + 2 * SM_W_ELEMS) * 2)

__global__ void __launch_bounds__(256) proj_kernel(
    const float* __restrict__ x_ing,
    const float* __restrict__ x_cmp,
    const float* __restrict__ W1,
    const float* __restrict__ b1,
    int n_ing, int n_cmp, int blocks_ing)
{
    const bool is_cmp = (blockIdx.x >= blocks_ing);
    const float* __restrict__ X = is_cmp ? x_cmp : x_ing;
    const float* __restrict__ W = is_cmp ? (W1 + HIDDEN * HIDDEN) : W1;
    __nv_bfloat16* __restrict__ P = is_cmp ? g_P_cmp : g_P_ing;
    const int nrows = is_cmp ? n_cmp : n_ing;
    const int bid = is_cmp ? (blockIdx.x - blocks_ing) : blockIdx.x;

    const int row0 = bid * 64;
    const int tid = threadIdx.x;
    const int wid = tid >> 5;

    extern __shared__ __align__(16) char sm[];
    __nv_bfloat16* A_hi = reinterpret_cast<__nv_bfloat16*>(sm);
    __nv_bfloat16* A_lo = A_hi + SM_A_ELEMS;
    __nv_bfloat16* W_hi = A_lo + SM_A_ELEMS;
    __nv_bfloat16* W_lo = W_hi + SM_W_ELEMS;

    // --- stage W half (128x128 fp32) split into bf16 hi/lo ---
    const float4* __restrict__ Wg4 = reinterpret_cast<const float4*>(W);
    #pragma unroll
    for (int i = 0; i < 16; i++) {
        const int v = tid + i * 256;       // 4096 float4 slots
        const int r = v >> 5;              // 0..127 (k index)
        const int c4 = v & 31;
        const float4 w = Wg4[v];
        const float wf[4] = {w.x, w.y, w.z, w.w};
        __nv_bfloat16 h[4], l[4];
        #pragma unroll
        for (int j = 0; j < 4; j++) {
            h[j] = __float2bfloat16_rn(wf[j]);
            l[j] = __float2bfloat16_rn(wf[j] - __bfloat162float(h[j]));
        }
        *reinterpret_cast<uint2*>(&W_hi[r * W_LD + c4 * 4]) = *reinterpret_cast<uint2*>(h);
        *reinterpret_cast<uint2*>(&W_lo[r * W_LD + c4 * 4]) = *reinterpret_cast<uint2*>(l);
    }

    // --- stage X tile (64x128 fp32) split into bf16 hi/lo ---
    const float4* __restrict__ X4 = reinterpret_cast<const float4*>(X);
    #pragma unroll
    for (int i = 0; i < 8; i++) {
        const int v = tid + i * 256;       // 2048 float4 slots
        const int r = v >> 5;              // 0..63
        const int c4 = v & 31;
        const int rs = min(row0 + r, nrows - 1);
        const float4 x = X4[(size_t)rs * 32 + c4];
        const float xf[4] = {x.x, x.y, x.z, x.w};
        __nv_bfloat16 h[4], l[4];
        #pragma unroll
        for (int j = 0; j < 4; j++) {
            h[j] = __float2bfloat16_rn(xf[j]);
            l[j] = __float2bfloat16_rn(xf[j] - __bfloat162float(h[j]));
        }
        *reinterpret_cast<uint2*>(&A_hi[r * A_LD + c4 * 4]) = *reinterpret_cast<uint2*>(h);
        *reinterpret_cast<uint2*>(&A_lo[r * A_LD + c4 * 4]) = *reinterpret_cast<uint2*>(l);
    }
    __syncthreads();

    // --- wmma mainloop: all operands from SMEM ---
    const int warp_r = (wid & 3) * 16;
    const int warp_c = (wid >> 2) * 64;

    wmma::fragment<wmma::accumulator, 16, 16, 16, float> acc[4];
    #pragma unroll
    for (int c = 0; c < 4; c++) wmma::fill_fragment(acc[c], 0.f);

    #pragma unroll
    for (int k = 0; k < 8; k++) {
        wmma::fragment<wmma::matrix_a, 16, 16, 16, __nv_bfloat16, wmma::row_major> a_hi, a_lo;
        wmma::load_matrix_sync(a_hi, &A_hi[warp_r * A_LD + k * 16], A_LD);
        wmma::load_matrix_sync(a_lo, &A_lo[warp_r * A_LD + k * 16], A_LD);
        #pragma unroll
        for (int c = 0; c < 4; c++) {
            const int col = warp_c + c * 16;
            wmma::fragment<wmma::matrix_b, 16, 16, 16, __nv_bfloat16, wmma::row_major> b_hi, b_lo;
            wmma::load_matrix_sync(b_hi, &W_hi[(k * 16) * W_LD + col], W_LD);
            wmma::load_matrix_sync(b_lo, &W_lo[(k * 16) * W_LD + col], W_LD);
            wmma::mma_sync(acc[c], a_hi, b_hi, acc[c]);
            wmma::mma_sync(acc[c], a_hi, b_lo, acc[c]);
            wmma::mma_sync(acc[c], a_lo, b_hi, acc[c]);
        }
    }

    // --- stage fp32 results (reuse A region: 64*128*4B = 32KB < 34.8KB) ---
    __syncthreads();
    float* Cst = reinterpret_cast<float*>(sm);
    #pragma unroll
    for (int c = 0; c < 4; c++)
        wmma::store_matrix_sync(&Cst[warp_r * 128 + warp_c + c * 16], acc[c],
                                128, wmma::mem_row_major);
    __syncthreads();

    // --- bias (cmp) + bf16 convert + store ---
    uint2* P2 = reinterpret_cast<uint2*>(P);
    #pragma unroll
    for (int i = 0; i < 8; i++) {
        const int v = tid + i * 256;
        const int r = v >> 5;
        const int c4 = v & 31;
        if (row0 + r < nrows) {
            float4 p = *reinterpret_cast<const float4*>(&Cst[r * 128 + c4 * 4]);
            if (is_cmp) {
                const float4 bv = reinterpret_cast<const float4*>(b1)[c4];
                p.x += bv.x; p.y += bv.y; p.z += bv.z; p.w += bv.w;
            }
            __nv_bfloat162 lo = __float22bfloat162_rn(make_float2(p.x, p.y));
            __nv_bfloat162 hi = __float22bfloat162_rn(make_float2(p.z, p.w));
            uint2 o;
            o.x = *reinterpret_cast<unsigned int*>(&lo);
            o.y = *reinterpret_cast<unsigned int*>(&hi);
            P2[(size_t)(row0 + r) * 32 + c4] = o;
        }
    }
}

// ---------------------------------------------------------------------------
// Edge kernel v6: 8 lanes/edge, 4 edges/group, contiguous 128B-line loads,
// __ldcg (L2-only) gathers — L1 hit rate ~3%, skip allocation/fill overhead.
// bit-shift bf16->fp32 unpack, fp32 FFMA dot, 3-shuffle reduce, float4 store.
// ---------------------------------------------------------------------------
__device__ __forceinline__ float edge_slice_dot(
    int s, int d, int t, const float* __restrict__ wv)
{
    const char* pa = (const char*)g_P_ing + (size_t)s * 256 + t * 16;
    const char* pb = (const char*)g_P_cmp + (size_t)d * 256 + t * 16;
    const uint4 al = __ldcg(reinterpret_cast<const uint4*>(pa));
    const uint4 ah = __ldcg(reinterpret_cast<const uint4*>(pa + 128));
    const uint4 bl = __ldcg(reinterpret_cast<const uint4*>(pb));
    const uint4 bh = __ldcg(reinterpret_cast<const uint4*>(pb + 128));

    const __nv_bfloat162 z2 = __float2bfloat162_rn(0.f);
    const unsigned av[8] = {al.x, al.y, al.z, al.w, ah.x, ah.y, ah.z, ah.w};
    const unsigned bv[8] = {bl.x, bl.y, bl.z, bl.w, bh.x, bh.y, bh.z, bh.w};

    float acc = 0.f;
    #pragma unroll
    for (int j = 0; j < 8; j++) {
        __nv_bfloat162 ha = *reinterpret_cast<const __nv_bfloat162*>(&av[j]);
        __nv_bfloat162 hb = *reinterpret_cast<const __nv_bfloat162*>(&bv[j]);
        __nv_bfloat162 h2 = __hmax2(__hadd2(ha, hb), z2);   // add + relu in bf16
        const unsigned hu = *reinterpret_cast<const unsigned*>(&h2);
        const float flo = __uint_as_float(hu << 16);
        const float fhi = __uint_as_float(hu & 0xFFFF0000u);
        acc = fmaf(flo, wv[2 * j], acc);
        acc = fmaf(fhi, wv[2 * j + 1], acc);
    }
    return acc;
}

__global__ void __launch_bounds__(256, 6) edge_kernel(
    const int* __restrict__ ei,
    const float* __restrict__ W2,
    const float* __restrict__ b2,
    float* __restrict__ out,
    int E)
{
    const int gid = (blockIdx.x * 256 + threadIdx.x) >> 3;
    const int t = threadIdx.x & 7;
    const int e0 = gid * 4;
    if (e0 >= E) return;

    const float4* W24 = reinterpret_cast<const float4*>(W2);
    const float4 wl0 = __ldg(W24 + 2 * t + 0);
    const float4 wl1 = __ldg(W24 + 2 * t + 1);
    const float4 wh0 = __ldg(W24 + 16 + 2 * t + 0);
    const float4 wh1 = __ldg(W24 + 16 + 2 * t + 1);
    const float wv[16] = {wl0.x, wl0.y, wl0.z, wl0.w,
                          wl1.x, wl1.y, wl1.z, wl1.w,
                          wh0.x, wh0.y, wh0.z, wh0.w,
                          wh1.x, wh1.y, wh1.z, wh1.w};
    const float b2v = __ldg(b2);

    int sv[4], dv[4];
    int ne;
    if (e0 + 4 <= E) {
        ne = 4;
        const int4 s4 = __ldg(reinterpret_cast<const int4*>(ei + e0));
        const int4 d4 = __ldg(reinterpret_cast<const int4*>(ei + E + e0));
        sv[0] = s4.x; sv[1] = s4.y; sv[2] = s4.z; sv[3] = s4.w;
        dv[0] = d4.x; dv[1] = d4.y; dv[2] = d4.z; dv[3] = d4.w;
    } else {
        ne = E - e0;
        for (int i = 0; i < ne; i++) {
            sv[i] = __ldg(ei + e0 + i);
            dv[i] = __ldg(ei + E + e0 + i);
        }
        for (int i = ne; i < 4; i++) { sv[i] = 0; dv[i] = 0; }
    }

    float acc[4];
    #pragma unroll
    for (int i = 0; i < 4; i++)
        acc[i] = edge_slice_dot(sv[i], dv[i], t, wv);

    #pragma unroll
    for (int i = 0; i < 4; i++) {
        acc[i] += __shfl_xor_sync(0xFFFFFFFFu, acc[i], 1);
        acc[i] += __shfl_xor_sync(0xFFFFFFFFu, acc[i], 2);
        acc[i] += __shfl_xor_sync(0xFFFFFFFFu, acc[i], 4);
    }

    if (t == 0) {
        if (ne == 4) {
            float4 o;
            o.x = 1.f / (1.f + __expf(-(acc[0] + b2v)));
            o.y = 1.f / (1.f + __expf(-(acc[1] + b2v)));
            o.z = 1.f / (1.f + __expf(-(acc[2] + b2v)));
            o.w = 1.f / (1.f + __expf(-(acc[3] + b2v)));
            *reinterpret_cast<float4*>(out + e0) = o;
        } else {
            for (int i = 0; i < ne; i++)
                out[e0 + i] = 1.f / (1.f + __expf(-(acc[i] + b2v)));
        }
    }
}

extern "C" void kernel_launch(void* const* d_in, const int* in_sizes, int n_in,
                              void* d_out, int out_size)
{
    const float* x_ing = (const float*)d_in[0];
    const float* x_cmp = (const float*)d_in[1];
    const int*   ei    = (const int*)d_in[2];
    const float* W1    = (const float*)d_in[3];
    const float* b1    = (const float*)d_in[4];
    const float* W2    = (const float*)d_in[5];
    const float* b2    = (const float*)d_in[6];
    float* out = (float*)d_out;

    const int n_ing = in_sizes[0] / HIDDEN;
    const int n_cmp = in_sizes[1] / HIDDEN;
    const int E     = in_sizes[2] / 2;

    cudaFuncSetAttribute(proj_kernel,
                         cudaFuncAttributeMaxDynamicSharedMemorySize,
                         PROJ_SMEM_BYTES);

    const int blocks_ing = (n_ing + 63) / 64;
    const int blocks_cmp = (n_cmp + 63) / 64;
    proj_kernel<<<blocks_ing + blocks_cmp, 256, PROJ_SMEM_BYTES>>>(
        x_ing, x_cmp, W1, b1, n_ing, n_cmp, blocks_ing);

    const int blocks = (E + 127) / 128;  // 128 edges per 256-thread block
    edge_kernel<<<blocks, 256>>>(ei, W2, b2, out, E);
}